// round 9
// baseline (speedup 1.0000x reference)
#include <cuda_runtime.h>

#define N_NODES 100000
#define E_EDGES 800000
#define H_HEADS 12
#define D_DIM 96
#define LRELU_SLOPE 0.2f

// ---------------- scratch ------------------------------------------------------
__device__ int    g_cnt[N_NODES];         // in-degree
__device__ int    g_base[N_NODES];        // CSR row starts
__device__ int    g_cursor[N_NODES];      // scatter cursors
__device__ int    g_srcs[E_EDGES];        // source ids, grouped by target
__device__ float4 g_norm4[N_NODES * 24];  // normalized rows [N,96]
__device__ int    g_total;                // running base counter
__device__ int    g_is64;

// ---------------- f32x2 helpers (Blackwell packed fp32 FMA) ---------------------
__device__ __forceinline__ void fma2(long long& d, long long a, long long b) {
    asm("fma.rn.f32x2 %0, %1, %2, %0;" : "+l"(d) : "l"(a), "l"(b));
}
__device__ __forceinline__ float2 upk(long long v) {
    float2 f;
    asm("mov.b64 {%0, %1}, %2;" : "=f"(f.x), "=f"(f.y) : "l"(v));
    return f;
}

// ---------------- setup: zero counts/total + dtype detect ------------------------
__global__ void setup_kernel(const int* __restrict__ ei32) {
    int i = blockIdx.x * blockDim.x + threadIdx.x;
    if (i < N_NODES) g_cnt[i] = 0;
    if (i == 0) {
        g_total = 0;
        int allz = 1;
        #pragma unroll
        for (int k = 1; k < 128; k += 2) allz &= (ei32[k] == 0);
        g_is64 = allz;
    }
}

// ---------------- count in-degrees straight from ei ------------------------------
__global__ void count_kernel(const void* __restrict__ ei) {
    int e = blockIdx.x * blockDim.x + threadIdx.x;
    if (e >= E_EDGES) return;
    int trg = g_is64 ? (int)((const long long*)ei)[E_EDGES + e]
                     : ((const int*)ei)[E_EDGES + e];
    atomicAdd(&g_cnt[trg], 1);
}

// ---------------- base assignment: warp scan + one atomic per warp ---------------
__global__ void base_kernel() {
    int i = blockIdx.x * blockDim.x + threadIdx.x;
    int lane = threadIdx.x & 31;
    int c = (i < N_NODES) ? g_cnt[i] : 0;

    int pre = c;
    #pragma unroll
    for (int off = 1; off < 32; off <<= 1) {
        int u = __shfl_up_sync(0xffffffffu, pre, off);
        if (lane >= off) pre += u;
    }
    int tot = __shfl_sync(0xffffffffu, pre, 31);
    int excl = pre - c;

    int wb = 0;
    if (lane == 0) wb = atomicAdd(&g_total, tot);
    wb = __shfl_sync(0xffffffffu, wb, 0);

    if (i < N_NODES) {
        int b = wb + excl;
        g_base[i] = b;
        g_cursor[i] = b;
    }
}

// ---------------- scatter straight from ei: 4B per edge --------------------------
__global__ void scatter_kernel(const void* __restrict__ ei) {
    int e = blockIdx.x * blockDim.x + threadIdx.x;
    if (e >= E_EDGES) return;
    int src, trg;
    if (g_is64) {
        src = (int)((const long long*)ei)[e];
        trg = (int)((const long long*)ei)[E_EDGES + e];
    } else {
        src = ((const int*)ei)[e];
        trg = ((const int*)ei)[E_EDGES + e];
    }
    int pos = atomicAdd(&g_cursor[trg], 1);
    g_srcs[pos] = src;
}

// ---------------- fused agg (unroll-4): score+exp+agg+normalize+RMS+ln -----------
// 16 lanes per node (12 active, one per head). Unroll-4 keeps 8 independent
// LDG.128 in flight per lane to cover L2 latency.
__global__ __launch_bounds__(256) void agg_norm_kernel(
        const float4* __restrict__ x4,
        const float*  __restrict__ a_src,
        const float*  __restrict__ a_trg,
        const float*  __restrict__ lnw) {
    int gid = blockIdx.x * 256 + threadIdx.x;   // n*16 + h
    int n = gid >> 4;
    int h = gid & 15;
    bool act = (h < 12);

    float4 as0, as1;
    float strg = 0.0f;
    int base = 0, deg = 0;
    if (act) {
        as0 = reinterpret_cast<const float4*>(a_src)[h * 2];
        as1 = reinterpret_cast<const float4*>(a_src)[h * 2 + 1];
        float4 at0 = reinterpret_cast<const float4*>(a_trg)[h * 2];
        float4 at1 = reinterpret_cast<const float4*>(a_trg)[h * 2 + 1];
        float4 xn0 = x4[n * 24 + h * 2];
        float4 xn1 = x4[n * 24 + h * 2 + 1];
        strg = xn0.x*at0.x + xn0.y*at0.y + xn0.z*at0.z + xn0.w*at0.w
             + xn1.x*at1.x + xn1.y*at1.y + xn1.z*at1.z + xn1.w*at1.w;
        base = g_base[n];
        deg  = g_cnt[n];
    }

    float4 a = make_float4(0.f, 0.f, 0.f, 0.f);
    float4 b = make_float4(0.f, 0.f, 0.f, 0.f);
    float  d = 0.f;

    int i = 0;
    for (; i + 4 <= deg; i += 4) {
        int s0 = g_srcs[base + i];
        int s1 = g_srcs[base + i + 1];
        int s2 = g_srcs[base + i + 2];
        int s3 = g_srcs[base + i + 3];
        float4 xa0 = x4[s0 * 24 + h * 2];
        float4 xb0 = x4[s0 * 24 + h * 2 + 1];
        float4 xa1 = x4[s1 * 24 + h * 2];
        float4 xb1 = x4[s1 * 24 + h * 2 + 1];
        float4 xa2 = x4[s2 * 24 + h * 2];
        float4 xb2 = x4[s2 * 24 + h * 2 + 1];
        float4 xa3 = x4[s3 * 24 + h * 2];
        float4 xb3 = x4[s3 * 24 + h * 2 + 1];

        float sc0 = strg
                  + xa0.x*as0.x + xa0.y*as0.y + xa0.z*as0.z + xa0.w*as0.w
                  + xb0.x*as1.x + xb0.y*as1.y + xb0.z*as1.z + xb0.w*as1.w;
        float sc1 = strg
                  + xa1.x*as0.x + xa1.y*as0.y + xa1.z*as0.z + xa1.w*as0.w
                  + xb1.x*as1.x + xb1.y*as1.y + xb1.z*as1.z + xb1.w*as1.w;
        float sc2 = strg
                  + xa2.x*as0.x + xa2.y*as0.y + xa2.z*as0.z + xa2.w*as0.w
                  + xb2.x*as1.x + xb2.y*as1.y + xb2.z*as1.z + xb2.w*as1.w;
        float sc3 = strg
                  + xa3.x*as0.x + xa3.y*as0.y + xa3.z*as0.z + xa3.w*as0.w
                  + xb3.x*as1.x + xb3.y*as1.y + xb3.z*as1.z + xb3.w*as1.w;
        sc0 = (sc0 >= 0.f) ? sc0 : LRELU_SLOPE * sc0;
        sc1 = (sc1 >= 0.f) ? sc1 : LRELU_SLOPE * sc1;
        sc2 = (sc2 >= 0.f) ? sc2 : LRELU_SLOPE * sc2;
        sc3 = (sc3 >= 0.f) ? sc3 : LRELU_SLOPE * sc3;
        float w0 = __expf(sc0);
        float w1 = __expf(sc1);
        float w2 = __expf(sc2);
        float w3 = __expf(sc3);

        d += (w0 + w1) + (w2 + w3);
        a.x += w0*xa0.x + w1*xa1.x + w2*xa2.x + w3*xa3.x;
        a.y += w0*xa0.y + w1*xa1.y + w2*xa2.y + w3*xa3.y;
        a.z += w0*xa0.z + w1*xa1.z + w2*xa2.z + w3*xa3.z;
        a.w += w0*xa0.w + w1*xa1.w + w2*xa2.w + w3*xa3.w;
        b.x += w0*xb0.x + w1*xb1.x + w2*xb2.x + w3*xb3.x;
        b.y += w0*xb0.y + w1*xb1.y + w2*xb2.y + w3*xb3.y;
        b.z += w0*xb0.z + w1*xb1.z + w2*xb2.z + w3*xb3.z;
        b.w += w0*xb0.w + w1*xb1.w + w2*xb2.w + w3*xb3.w;
    }
    for (; i < deg; i++) {
        int s0 = g_srcs[base + i];
        float4 xa0 = x4[s0 * 24 + h * 2];
        float4 xb0 = x4[s0 * 24 + h * 2 + 1];
        float sc0 = strg
                  + xa0.x*as0.x + xa0.y*as0.y + xa0.z*as0.z + xa0.w*as0.w
                  + xb0.x*as1.x + xb0.y*as1.y + xb0.z*as1.z + xb0.w*as1.w;
        sc0 = (sc0 >= 0.f) ? sc0 : LRELU_SLOPE * sc0;
        float w0 = __expf(sc0);
        d += w0;
        a.x += w0 * xa0.x; a.y += w0 * xa0.y; a.z += w0 * xa0.z; a.w += w0 * xa0.w;
        b.x += w0 * xb0.x; b.y += w0 * xb0.y; b.z += w0 * xb0.z; b.w += w0 * xb0.w;
    }

    float r = __fdividef(1.0f, d + 1e-16f);
    a.x *= r; a.y *= r; a.z *= r; a.w *= r;
    b.x *= r; b.y *= r; b.z *= r; b.w *= r;

    float ss = act ? (a.x*a.x + a.y*a.y + a.z*a.z + a.w*a.w +
                      b.x*b.x + b.y*b.y + b.z*b.z + b.w*b.w) : 0.0f;
    ss += __shfl_xor_sync(0xffffffffu, ss, 8);
    ss += __shfl_xor_sync(0xffffffffu, ss, 4);
    ss += __shfl_xor_sync(0xffffffffu, ss, 2);
    ss += __shfl_xor_sync(0xffffffffu, ss, 1);
    float rms = rsqrtf(ss * (1.0f / 96.0f) + 1e-6f);

    if (act) {
        float4 l0 = reinterpret_cast<const float4*>(lnw)[h * 2];
        float4 l1 = reinterpret_cast<const float4*>(lnw)[h * 2 + 1];
        float4 o0 = make_float4(a.x*rms*l0.x, a.y*rms*l0.y, a.z*rms*l0.z, a.w*rms*l0.w);
        float4 o1 = make_float4(b.x*rms*l1.x, b.y*rms*l1.y, b.z*rms*l1.z, b.w*rms*l1.w);
        g_norm4[n * 24 + h * 2]     = o0;
        g_norm4[n * 24 + h * 2 + 1] = o1;
    }
}

// ---------------- GEMM via f32x2: out = x + norm @ W^T (64 nodes / block) --------
__global__ __launch_bounds__(256) void gemm_kernel(
        const float* __restrict__ x,
        const float* __restrict__ wproj,
        float* __restrict__ out) {
    __shared__ float4 Wp[96][25];
    __shared__ float4 sm_n[64][25];

    int tid = threadIdx.x;
    int node0 = blockIdx.x * 64;

    const float4* w4 = reinterpret_cast<const float4*>(wproj);
    for (int i = tid; i < 96 * 24; i += 256) {
        int r = i / 24, c2 = i - r * 24;
        Wp[r][c2] = w4[i];
    }
    for (int i = tid; i < 64 * 24; i += 256) {
        int nd = i / 24, c2 = i - nd * 24;
        sm_n[nd][c2] = g_norm4[(node0 + nd) * 24 + c2];
    }
    __syncthreads();

    int wp = tid >> 5, lane = tid & 31;   // 8 warps x 8 nodes each
    long long acc2[8][3];
    #pragma unroll
    for (int aa = 0; aa < 8; aa++)
        #pragma unroll
        for (int bb = 0; bb < 3; bb++) acc2[aa][bb] = 0LL;

    #pragma unroll 2
    for (int k = 0; k < 24; k++) {
        longlong2 w0 = *reinterpret_cast<const longlong2*>(&Wp[lane][k]);
        longlong2 w1 = *reinterpret_cast<const longlong2*>(&Wp[lane + 32][k]);
        longlong2 w2 = *reinterpret_cast<const longlong2*>(&Wp[lane + 64][k]);
        #pragma unroll
        for (int aa = 0; aa < 8; aa++) {
            longlong2 nb = *reinterpret_cast<const longlong2*>(&sm_n[wp * 8 + aa][k]);
            fma2(acc2[aa][0], nb.x, w0.x); fma2(acc2[aa][0], nb.y, w0.y);
            fma2(acc2[aa][1], nb.x, w1.x); fma2(acc2[aa][1], nb.y, w1.y);
            fma2(acc2[aa][2], nb.x, w2.x); fma2(acc2[aa][2], nb.y, w2.y);
        }
    }

    #pragma unroll
    for (int aa = 0; aa < 8; aa++) {
        int n = node0 + wp * 8 + aa;
        float2 p0 = upk(acc2[aa][0]);
        float2 p1 = upk(acc2[aa][1]);
        float2 p2 = upk(acc2[aa][2]);
        out[n * 96 + lane]      = x[n * 96 + lane]      + (p0.x + p0.y);
        out[n * 96 + lane + 32] = x[n * 96 + lane + 32] + (p1.x + p1.y);
        out[n * 96 + lane + 64] = x[n * 96 + lane + 64] + (p2.x + p2.y);
    }
}

// ---------------- launch -----------------------------------------------------------
extern "C" void kernel_launch(void* const* d_in, const int* in_sizes, int n_in,
                              void* d_out, int out_size) {
    const float* x   = (const float*)d_in[0];
    const void*  ei  = d_in[1];
    const float* w   = (const float*)d_in[2];
    const float* ss  = (const float*)d_in[3];
    const float* st  = (const float*)d_in[4];
    const float* lnw = (const float*)d_in[5];
    float*       out = (float*)d_out;

    setup_kernel<<<(N_NODES + 255) / 256, 256>>>((const int*)ei);
    count_kernel<<<(E_EDGES + 255) / 256, 256>>>(ei);
    base_kernel<<<(N_NODES + 255) / 256, 256>>>();
    scatter_kernel<<<(E_EDGES + 255) / 256, 256>>>(ei);
    agg_norm_kernel<<<(N_NODES * 16) / 256, 256>>>(
        reinterpret_cast<const float4*>(x), ss, st, lnw);
    gemm_kernel<<<(N_NODES + 63) / 64, 256>>>(x, w, out);
}